// round 1
// baseline (speedup 1.0000x reference)
#include <cuda_runtime.h>
#include <math.h>

// Problem constants (fixed by the dataset)
#define Dq 256
#define Hq 256
#define Kq 11
#define MT 16          // rows per CTA
#define NTHREADS 256   // one thread per output column

// Dynamic smem layout (in floats):
//   Xs : [256][16]            4096   (input x tile, transposed [d][m])
//   Hs : [256][16]            4096   (hidden buffer / phase-2 scratch)
//   TXs: [256][16] or z[16][256] 4096
//   ZT : [11][16][256]       45056   (zt vectors, [k][m][j])
// total = 57344 floats = 229376 bytes (< 232448 max dynamic)
#define XS_OFF 0
#define HS_OFF 4096
#define TX_OFF 8192
#define ZT_OFF 12288
#define SMEM_FLOATS 57344

__device__ __forceinline__ float gelu_exact(float v) {
    return 0.5f * v * (1.0f + erff(v * 0.70710678118654752f));
}

// O[j, m] = act( sum_d In[d][m] * W[d*256 + j] + bias[j] )
// In layout: In[d*MT + m]. Output written at Out[m*om + j*oj].
__device__ __forceinline__ void gemm_step(
    const float* __restrict__ W, const float* __restrict__ bias,
    const float* __restrict__ In, float* __restrict__ Out,
    int j, bool do_gelu, int om, int oj)
{
    float acc[MT];
    {
        float b = bias[j];
#pragma unroll
        for (int m = 0; m < MT; ++m) acc[m] = b;
    }

    // double-buffered weight column loads (8-deep MLP against L2 latency)
    float w[8];
#pragma unroll
    for (int u = 0; u < 8; ++u) w[u] = W[u * 256 + j];

    for (int d = 0; d < 256; d += 8) {
        float wn[8];
        if (d + 8 < 256) {
#pragma unroll
            for (int u = 0; u < 8; ++u) wn[u] = W[(d + 8 + u) * 256 + j];
        }
#pragma unroll
        for (int u = 0; u < 8; ++u) {
            const float4* xr = reinterpret_cast<const float4*>(In + (d + u) * MT);
            float wu = w[u];
#pragma unroll
            for (int q = 0; q < 4; ++q) {
                float4 xv = xr[q];   // broadcast LDS.128 (all lanes same addr)
                acc[q * 4 + 0] = fmaf(xv.x, wu, acc[q * 4 + 0]);
                acc[q * 4 + 1] = fmaf(xv.y, wu, acc[q * 4 + 1]);
                acc[q * 4 + 2] = fmaf(xv.z, wu, acc[q * 4 + 2]);
                acc[q * 4 + 3] = fmaf(xv.w, wu, acc[q * 4 + 3]);
            }
        }
#pragma unroll
        for (int u = 0; u < 8; ++u) w[u] = wn[u];
    }

#pragma unroll
    for (int m = 0; m < MT; ++m) {
        float v = acc[m];
        if (do_gelu) v = gelu_exact(v);
        Out[m * om + j * oj] = v;
    }
}

// dot over 256 elements, conflict-free (lane-strided), result valid on lane 0
__device__ __forceinline__ float warp_dot256(const float* __restrict__ a,
                                             const float* __restrict__ b, int lane)
{
    float s = 0.f;
#pragma unroll
    for (int u = 0; u < 8; ++u) {
        int j = u * 32 + lane;
        s = fmaf(a[j], b[j], s);
    }
#pragma unroll
    for (int off = 16; off; off >>= 1)
        s += __shfl_down_sync(0xffffffffu, s, off);
    return s;
}

extern __shared__ float smem[];

__global__ void __launch_bounds__(NTHREADS, 1)
neutralad_fused_kernel(
    const float* __restrict__ x,
    const float* __restrict__ Tw1, const float* __restrict__ Tb1,
    const float* __restrict__ Tw2, const float* __restrict__ Tb2,
    const float* __restrict__ Ew1, const float* __restrict__ Eb1,
    const float* __restrict__ Ew2, const float* __restrict__ Eb2,
    float* __restrict__ out)
{
    const int j = threadIdx.x;           // output column / d index
    const long long b0 = (long long)blockIdx.x * MT;

    float* Xs  = smem + XS_OFF;
    float* Hs  = smem + HS_OFF;
    float* TXs = smem + TX_OFF;
    float* ZTs = smem + ZT_OFF;

    // ---- load X tile, transposed: Xs[d][m] ----
#pragma unroll
    for (int m = 0; m < MT; ++m)
        Xs[j * MT + m] = x[(b0 + m) * Dq + j];
    __syncthreads();

    // ---- K transforms + their encoders ----
    for (int k = 0; k < Kq; ++k) {
        // h1 = gelu(x @ Tw1_k + Tb1_k)
        gemm_step(Tw1 + (size_t)k * Dq * Hq, Tb1 + k * Hq, Xs, Hs, j, true, 1, MT);
        __syncthreads();
        // tx = h1 @ Tw2_k + Tb2_k
        gemm_step(Tw2 + (size_t)k * Hq * Dq, Tb2 + k * Dq, Hs, TXs, j, false, 1, MT);
        __syncthreads();
        // e1 = gelu(tx @ Ew1 + Eb1)
        gemm_step(Ew1, Eb1, TXs, Hs, j, true, 1, MT);
        __syncthreads();
        // zt_k = e1 @ Ew2 + Eb2  -> ZT[k][m][j] ([m][j] layout, conflict-free writes)
        gemm_step(Ew2, Eb2, Hs, ZTs + (size_t)k * MT * Hq, j, false, Hq, 1);
        __syncthreads();
    }

    // ---- z = enc(x), stored into TXs as [m][j] ----
    gemm_step(Ew1, Eb1, Xs, Hs, j, true, 1, MT);
    __syncthreads();
    gemm_step(Ew2, Eb2, Hs, TXs, j, false, Hq, 1);
    __syncthreads();

    // ---- phase 2: per-row similarity scoring ----
    // Hs is free now -> scratch [16][256] per-row dot storage:
    //   [l*11+k] pair dots (symmetric), [132+k] z·zt_k, [144+k] ||zt_k||, [160] ||z||
    const int warp = threadIdx.x >> 5;
    const int lane = threadIdx.x & 31;

#pragma unroll
    for (int mi = 0; mi < 2; ++mi) {
        const int m = warp * 2 + mi;
        float* sc = Hs + m * 256;
        const float* zrow = TXs + m * Hq;

        // norms of zt_k
        for (int k = 0; k < Kq; ++k) {
            const float* a = ZTs + ((size_t)k * MT + m) * Hq;
            float s = warp_dot256(a, a, lane);
            if (lane == 0) sc[144 + k] = sqrtf(s);
        }
        // norm of z
        {
            float s = warp_dot256(zrow, zrow, lane);
            if (lane == 0) sc[160] = sqrtf(s);
        }
        // z · zt_k
        for (int k = 0; k < Kq; ++k) {
            const float* a = ZTs + ((size_t)k * MT + m) * Hq;
            float s = warp_dot256(zrow, a, lane);
            if (lane == 0) sc[132 + k] = s;
        }
        // zt_l · zt_k (l < k), stored symmetric
        for (int l = 0; l < Kq; ++l) {
            const float* a = ZTs + ((size_t)l * MT + m) * Hq;
            for (int k = l + 1; k < Kq; ++k) {
                const float* bb = ZTs + ((size_t)k * MT + m) * Hq;
                float s = warp_dot256(a, bb, lane);
                if (lane == 0) { sc[l * 11 + k] = s; sc[k * 11 + l] = s; }
            }
        }
        __syncwarp();

        // score_m = sum_k log1p(neg_k / sim_z_k)
        float term = 0.f;
        if (lane < Kq) {
            const int k = lane;
            const float nz = sc[160];
            const float nk = sc[144 + k];
            const float sim = expf(sc[132 + k] / fmaxf(nz * nk, 1e-8f));
            float neg = 0.f;
#pragma unroll
            for (int l = 0; l < Kq; ++l) {
                if (l == k) continue;
                const float nl = sc[144 + l];
                neg += expf(sc[l * 11 + k] / fmaxf(nl * nk, 1e-8f));
            }
            term = log1pf(neg / sim);
        }
#pragma unroll
        for (int off = 16; off; off >>= 1)
            term += __shfl_down_sync(0xffffffffu, term, off);
        if (lane == 0) out[b0 + m] = term;
    }
}

extern "C" void kernel_launch(void* const* d_in, const int* in_sizes, int n_in,
                              void* d_out, int out_size)
{
    const float* x   = (const float*)d_in[0];
    const float* Tw1 = (const float*)d_in[1];
    const float* Tb1 = (const float*)d_in[2];
    const float* Tw2 = (const float*)d_in[3];
    const float* Tb2 = (const float*)d_in[4];
    const float* Ew1 = (const float*)d_in[5];
    const float* Eb1 = (const float*)d_in[6];
    const float* Ew2 = (const float*)d_in[7];
    const float* Eb2 = (const float*)d_in[8];
    float* out = (float*)d_out;

    const int B = in_sizes[0] / Dq;
    const int grid = B / MT;
    const size_t smem_bytes = SMEM_FLOATS * sizeof(float);

    cudaFuncSetAttribute(neutralad_fused_kernel,
                         cudaFuncAttributeMaxDynamicSharedMemorySize,
                         (int)smem_bytes);

    neutralad_fused_kernel<<<grid, NTHREADS, smem_bytes>>>(
        x, Tw1, Tb1, Tw2, Tb2, Ew1, Eb1, Ew2, Eb2, out);
}